// round 1
// baseline (speedup 1.0000x reference)
#include <cuda_runtime.h>
#include <cuda_bf16.h>
#include <cstdint>

#define B_   128
#define I_   64
#define S_   2048
#define H_   128
#define O_   64
#define G4H  512

#define GB   16            // batch groups (clusters)
#define GH   8             // h groups (CTAs per cluster)
#define BPG  (B_/GB)       // 8 batches per CTA
#define HPG  (H_/GH)       // 16 h-indices per CTA
#define CPC  (4*HPG)       // 64 gate columns per CTA
#define KOUT (I_+H_)       // 192
#define KIN  (2*H_)        // 256

// ---------------- device scratch (static: no allocation) ----------------
__device__ float g_xT[(size_t)S_ * B_ * I_];   // 64 MB  [t][b*I+i]
__device__ float g_hs[(size_t)B_ * S_ * H_];   // 128 MB [b][t][h]
__device__ float g_h  [B_ * H_];
__device__ float g_xin[B_ * H_];
__device__ float g_hin[B_ * H_];

// ---------------- helpers ----------------
__device__ __forceinline__ float sigf(float x) {
    return __fdividef(1.0f, 1.0f + __expf(-x));
}
__device__ __forceinline__ float tanh_(float x) {
    // tanh(x) = 2*sigmoid(2x) - 1  (abs err ~1e-6, harmless for 1e-3 tolerance)
    return __fdividef(2.0f, 1.0f + __expf(-2.0f * x)) - 1.0f;
}
__device__ __forceinline__ void cluster_sync() {
    asm volatile("barrier.cluster.arrive.aligned;\n\t"
                 "barrier.cluster.wait.aligned;" ::: "memory");
}

// ---------------- transpose x (B,I,S) -> xT (S, B*I) ----------------
__global__ void transpose_x_kernel(const float* __restrict__ x) {
    __shared__ float tile[32][33];
    int cb = blockIdx.x * 32;   // along S
    int rb = blockIdx.y * 32;   // along R = B*I
    int tx = threadIdx.x, ty = threadIdx.y;
#pragma unroll
    for (int j = 0; j < 32; j += 8)
        tile[ty + j][tx] = x[(size_t)(rb + ty + j) * S_ + cb + tx];
    __syncthreads();
#pragma unroll
    for (int j = 0; j < 32; j += 8)
        g_xT[(size_t)(cb + ty + j) * (B_ * I_) + rb + tx] = tile[tx][ty + j];
}

// ---------------- persistent recurrent kernel ----------------
// grid (GH, GB), cluster (GH,1,1): cluster = one batch-group of 8 H-CTAs.
#define SMEM_FLOATS (KOUT*CPC + KIN*CPC + BPG*KOUT + BPG*KIN + BPG*CPC + 3*BPG*HPG + 2*CPC)
#define SMEM_BYTES  (SMEM_FLOATS * 4)

__global__ void __cluster_dims__(GH, 1, 1) __launch_bounds__(256, 1)
nlstm_recurrent(const float* __restrict__ Wx_out, const float* __restrict__ Wh_out,
                const float* __restrict__ b_out,
                const float* __restrict__ Wx_in,  const float* __restrict__ Wh_in,
                const float* __restrict__ b_in)
{
    extern __shared__ float smem[];
    float* sWout = smem;                       // [KOUT][CPC]
    float* sWin  = sWout + KOUT * CPC;         // [KIN][CPC]
    float* s_xh  = sWin  + KIN  * CPC;         // [BPG][KOUT]
    float* s_xh2 = s_xh  + BPG * KOUT;         // [BPG][KIN]
    float* s_gat = s_xh2 + BPG * KIN;          // [BPG][CPC]
    float* s_o   = s_gat + BPG * CPC;          // [BPG][HPG]
    float* s_c   = s_o   + BPG * HPG;
    float* s_cn  = s_c   + BPG * HPG;
    float* s_bo  = s_cn  + BPG * HPG;          // [CPC]
    float* s_bi  = s_bo  + CPC;                // [CPC]

    const int tid = threadIdx.x;
    const int hj  = blockIdx.x;        // 0..7  (H group)
    const int bi  = blockIdx.y;        // 0..15 (batch group)
    const int bg0 = bi * BPG;
    const int hg0 = hj * HPG;

    // ---- load weight slices into SMEM (one time) ----
    for (int idx = tid; idx < KOUT * CPC; idx += 256) {
        int k = idx >> 6, c = idx & 63;
        int gc = (c >> 4) * H_ + hg0 + (c & 15);
        sWout[idx] = (k < I_) ? Wx_out[k * G4H + gc] : Wh_out[(k - I_) * G4H + gc];
    }
    for (int idx = tid; idx < KIN * CPC; idx += 256) {
        int k = idx >> 6, c = idx & 63;
        int gc = (c >> 4) * H_ + hg0 + (c & 15);
        sWin[idx] = (k < H_) ? Wx_in[k * G4H + gc] : Wh_in[(k - H_) * G4H + gc];
    }
    if (tid < CPC) {
        int gc = (tid >> 4) * H_ + hg0 + (tid & 15);
        s_bo[tid] = b_out[gc];
        s_bi[tid] = b_in[gc];
    }
    // ---- zero local state and our slice of global h ----
    for (int idx = tid; idx < BPG * HPG; idx += 256) { s_c[idx] = 0.0f; s_cn[idx] = 0.0f; }
    if (tid < BPG * HPG) {
        int b = tid >> 4, hl = tid & 15;
        __stcg(&g_h[(bg0 + b) * H_ + hg0 + hl], 0.0f);
    }
    __syncthreads();
    cluster_sync();   // h fully zeroed across the cluster before step 0

    const int c  = tid & 63;
    const int r  = tid >> 6;       // 0..3
    const int b0 = 2 * r, b1 = 2 * r + 1;

    for (int t = 0; t < S_; t++) {
        // ---- phase 1: stage [xt | h] per batch row ----
        const float* xTrow = g_xT + (size_t)t * (B_ * I_) + bg0 * I_;
        for (int idx = tid; idx < BPG * KOUT; idx += 256) {
            int b = idx / KOUT;
            int k = idx - b * KOUT;
            s_xh[idx] = (k < I_) ? xTrow[b * I_ + k]
                                 : __ldcg(&g_h[(bg0 + b) * H_ + (k - I_)]);
        }
        __syncthreads();

        // ---- outer matvec: gates = [xt|h] @ W_out + b_out ----
        {
            float a0 = s_bo[c], a1 = a0;
            const float*  wp = sWout + c;
            const float4* x0 = (const float4*)(s_xh + b0 * KOUT);
            const float4* x1 = (const float4*)(s_xh + b1 * KOUT);
#pragma unroll 8
            for (int k4 = 0; k4 < KOUT / 4; k4++) {
                float4 v0 = x0[k4];
                float4 v1 = x1[k4];
                float w0 = wp[(4 * k4 + 0) * CPC];
                float w1 = wp[(4 * k4 + 1) * CPC];
                float w2 = wp[(4 * k4 + 2) * CPC];
                float w3 = wp[(4 * k4 + 3) * CPC];
                a0 = fmaf(w0, v0.x, a0); a0 = fmaf(w1, v0.y, a0);
                a0 = fmaf(w2, v0.z, a0); a0 = fmaf(w3, v0.w, a0);
                a1 = fmaf(w0, v1.x, a1); a1 = fmaf(w1, v1.y, a1);
                a1 = fmaf(w2, v1.z, a1); a1 = fmaf(w3, v1.w, a1);
            }
            s_gat[b0 * CPC + c] = a0;
            s_gat[b1 * CPC + c] = a1;
        }
        __syncthreads();

        // ---- act 1: i,f,o,g -> x_in, h_in (published to cluster) ----
        if (tid < BPG * HPG) {
            int b = tid >> 4, hl = tid & 15;
            const float* gr = s_gat + b * CPC;
            float iv = sigf(gr[hl]);
            float fv = sigf(gr[HPG + hl]);
            float ov = sigf(gr[2 * HPG + hl]);
            float gv = tanh_(gr[3 * HPG + hl]);
            float xin = iv * gv;
            float hin = fv * s_c[tid];
            s_o[tid] = ov;
            int gidx = (bg0 + b) * H_ + hg0 + hl;
            __stcg(&g_xin[gidx], xin);
            __stcg(&g_hin[gidx], hin);
        }
        __syncthreads();
        cluster_sync();

        // ---- phase 2: stage [x_in | h_in] ----
        for (int idx = tid; idx < BPG * KIN; idx += 256) {
            int b = idx >> 8;
            int k = idx & 255;
            int gb = (bg0 + b) * H_;
            s_xh2[idx] = (k < H_) ? __ldcg(&g_xin[gb + k])
                                  : __ldcg(&g_hin[gb + (k - H_)]);
        }
        __syncthreads();

        // ---- inner matvec: gi = [x_in|h_in] @ W_in + b_in ----
        {
            float a0 = s_bi[c], a1 = a0;
            const float*  wp = sWin + c;
            const float4* x0 = (const float4*)(s_xh2 + b0 * KIN);
            const float4* x1 = (const float4*)(s_xh2 + b1 * KIN);
#pragma unroll 8
            for (int k4 = 0; k4 < KIN / 4; k4++) {
                float4 v0 = x0[k4];
                float4 v1 = x1[k4];
                float w0 = wp[(4 * k4 + 0) * CPC];
                float w1 = wp[(4 * k4 + 1) * CPC];
                float w2 = wp[(4 * k4 + 2) * CPC];
                float w3 = wp[(4 * k4 + 3) * CPC];
                a0 = fmaf(w0, v0.x, a0); a0 = fmaf(w1, v0.y, a0);
                a0 = fmaf(w2, v0.z, a0); a0 = fmaf(w3, v0.w, a0);
                a1 = fmaf(w0, v1.x, a1); a1 = fmaf(w1, v1.y, a1);
                a1 = fmaf(w2, v1.z, a1); a1 = fmaf(w3, v1.w, a1);
            }
            s_gat[b0 * CPC + c] = a0;
            s_gat[b1 * CPC + c] = a1;
        }
        __syncthreads();

        // ---- act 2: inner cell update, outer cell, new hidden ----
        if (tid < BPG * HPG) {
            int b = tid >> 4, hl = tid & 15;
            const float* gr = s_gat + b * CPC;
            float iiv = sigf(gr[hl]);
            float fiv = sigf(gr[HPG + hl]);
            float oiv = sigf(gr[2 * HPG + hl]);
            float ggv = tanh_(gr[3 * HPG + hl]);
            float cn  = fiv * s_cn[tid] + iiv * ggv;
            float cv  = oiv * tanh_(cn);
            float hv  = s_o[tid] * tanh_(cv);
            s_cn[tid] = cn;
            s_c[tid]  = cv;
            int bglob = bg0 + b, hgl = hg0 + hl;
            __stcg(&g_h[bglob * H_ + hgl], hv);
            g_hs[((size_t)bglob * S_ + t) * H_ + hgl] = hv;
        }
        __syncthreads();
        cluster_sync();   // publish h for next step's phase 1
    }
}

// ---------------- final projection: out = hs @ W_lin^T + b_lin ----------------
__global__ __launch_bounds__(256) void out_proj_kernel(const float* __restrict__ W_lin,
                                                       const float* __restrict__ b_lin,
                                                       float* __restrict__ out)
{
    __shared__ float sH[64][129];      // padded: conflict-free column reads
    __shared__ float sW[O_][H_];
    int m0  = blockIdx.x * 64;
    int tid = threadIdx.x;

    for (int idx = tid; idx < O_ * H_; idx += 256)
        sW[idx >> 7][idx & 127] = W_lin[idx];
    for (int idx = tid; idx < 64 * H_; idx += 256) {
        int rr = idx >> 7, hh = idx & 127;
        sH[rr][hh] = g_hs[(size_t)(m0 + rr) * H_ + hh];
    }
    __syncthreads();

    int row = tid & 63, og = tid >> 6;   // 4 groups x 16 output cols
    float acc[16];
#pragma unroll
    for (int j = 0; j < 16; j++) acc[j] = b_lin[16 * og + j];
#pragma unroll 4
    for (int h = 0; h < H_; h++) {
        float v = sH[row][h];
#pragma unroll
        for (int j = 0; j < 16; j++)
            acc[j] = fmaf(v, sW[16 * og + j][h], acc[j]);
    }
    float* orow = out + (size_t)(m0 + row) * O_ + 16 * og;
#pragma unroll
    for (int j = 0; j < 16; j++) orow[j] = acc[j];
}

// ---------------- launch ----------------
extern "C" void kernel_launch(void* const* d_in, const int* in_sizes, int n_in,
                              void* d_out, int out_size)
{
    const float* x      = (const float*)d_in[0];
    const float* Wx_out = (const float*)d_in[1];
    const float* Wh_out = (const float*)d_in[2];
    const float* b_out  = (const float*)d_in[3];
    const float* Wx_in  = (const float*)d_in[4];
    const float* Wh_in  = (const float*)d_in[5];
    const float* b_in   = (const float*)d_in[6];
    const float* W_lin  = (const float*)d_in[7];
    const float* b_lin  = (const float*)d_in[8];
    float* out = (float*)d_out;

    transpose_x_kernel<<<dim3(S_ / 32, (B_ * I_) / 32), dim3(32, 8)>>>(x);

    (void)cudaFuncSetAttribute(nlstm_recurrent,
                               cudaFuncAttributeMaxDynamicSharedMemorySize, SMEM_BYTES);
    nlstm_recurrent<<<dim3(GH, GB), 256, SMEM_BYTES>>>(Wx_out, Wh_out, b_out,
                                                       Wx_in, Wh_in, b_in);

    out_proj_kernel<<<(B_ * S_) / 64, 256>>>(W_lin, b_lin, out);
}

// round 5
// speedup vs baseline: 1.5167x; 1.5167x over previous
#include <cuda_runtime.h>
#include <cuda_bf16.h>
#include <cstdint>

#define B_   128
#define I_   64
#define S_   2048
#define H_   128
#define O_   64
#define G4H  512

#define GB   16            // batch groups (clusters)
#define GH   8             // CTAs per cluster (h groups / t-slices)
#define BPG  (B_/GB)       // 8 batches per cluster
#define HPG  (H_/GH)       // 16 h-indices per CTA
#define CPC  (4*HPG)       // 64 gate columns per CTA
#define KOUT (I_+H_)       // 192
#define KIN  (2*H_)        // 256
#define THREADS 512

// ---------------- device scratch (static) ----------------
__device__ float g_xT[(size_t)GB * S_ * (BPG * I_)];  // [bi][t][b*64+i]  64MB
__device__ float g_hs[(size_t)B_ * S_ * H_];          // [b][t][h]       128MB
__device__ float g_h  [B_ * H_];
__device__ float g_xin[B_ * H_];
__device__ float g_hin[B_ * H_];

// ---------------- smem layout (floats) ----------------
#define OFF_W1   0                     // [48 chunks][64 c] float4 -> 12288 f
#define OFF_W2   12288                 // [64 chunks][64 c] float4 -> 16384 f
#define OFF_X1   28672                 // [192][12]  -> 2304 f
#define OFF_X2   30976                 // [256][12]  -> 3072 f
#define OFF_PART 34048                 // [8][8][80] -> 5120 f
#define OFF_O    39168                 // 128
#define OFF_C    39296                 // 128
#define OFF_CN   39424                 // 128
#define OFF_B1   39552                 // 64
#define OFF_B2   39616                 // 64
#define SMEM_FLOATS 39680
#define SMEM_BYTES  (SMEM_FLOATS * 4)  // 158720 B

__device__ __forceinline__ float sigf(float x) {
    return __fdividef(1.0f, 1.0f + __expf(-x));
}
__device__ __forceinline__ float tanh_(float x) {
    return __fdividef(2.0f, 1.0f + __expf(-2.0f * x)) - 1.0f;
}
__device__ __forceinline__ void cluster_sync() {
    asm volatile("barrier.cluster.arrive.aligned;\n\t"
                 "barrier.cluster.wait.aligned;" ::: "memory");
}

__global__ void __cluster_dims__(GH, 1, 1) __launch_bounds__(THREADS, 1)
nlstm_fused(const float* __restrict__ x,
            const float* __restrict__ Wx_out, const float* __restrict__ Wh_out,
            const float* __restrict__ b_out,
            const float* __restrict__ Wx_in,  const float* __restrict__ Wh_in,
            const float* __restrict__ b_in,
            const float* __restrict__ W_lin,  const float* __restrict__ b_lin,
            float* __restrict__ out)
{
    extern __shared__ float smem[];
    const int tid = threadIdx.x;
    const int hj  = blockIdx.x;        // 0..7
    const int bi  = blockIdx.y;        // 0..15
    const int bg0 = bi * BPG;
    const int hg0 = hj * HPG;

    // ================= phase 0: cluster-local transpose =================
    // x slice for this batch-group: rows r = b*64+i (512 rows) x S_ cols.
    // This CTA handles t in [hj*256, hj*256+256). tile[r 64][t 256] pad 257.
    {
        const float* xbg  = x + (size_t)bg0 * I_ * S_;
        float*       xTbg = g_xT + (size_t)bi * S_ * (BPG * I_);
        const int t0 = hj * 256;
        float* tile = smem;                       // [64][257] = 16448 f
        for (int rt = 0; rt < 8; rt++) {
            int r0 = rt * 64;
            for (int idx = tid; idx < 64 * 256; idx += THREADS) {
                int r = idx >> 8, tt = idx & 255;               // coalesced read
                tile[r * 257 + tt] = xbg[(size_t)(r0 + r) * S_ + t0 + tt];
            }
            __syncthreads();
            for (int idx = tid; idx < 64 * 256; idx += THREADS) {
                int tt = idx >> 6, r = idx & 63;                // coalesced write
                xTbg[(size_t)(t0 + tt) * (BPG * I_) + r0 + r] = tile[r * 257 + tt];
            }
            __syncthreads();
        }
    }

    // ================= phase 1: load weights / biases / init state =================
    float* sW1 = smem + OFF_W1;
    float* sW2 = smem + OFF_W2;
    float* sX1 = smem + OFF_X1;
    float* sX2 = smem + OFF_X2;
    float* sP  = smem + OFF_PART;
    float* sO  = smem + OFF_O;
    float* sC  = smem + OFF_C;
    float* sCN = smem + OFF_CN;
    float* sB1 = smem + OFF_B1;
    float* sB2 = smem + OFF_B2;

    // W1: [k4][c][4]  k = k4*4+e, gate col gc = (c>>4)*H + hg0 + (c&15)
    for (int idx = tid; idx < KOUT * CPC; idx += THREADS) {
        int k4 = idx >> 8, c = (idx >> 2) & 63, e = idx & 3;
        int k  = k4 * 4 + e;
        int gc = (c >> 4) * H_ + hg0 + (c & 15);
        sW1[idx] = (k < I_) ? Wx_out[k * G4H + gc] : Wh_out[(k - I_) * G4H + gc];
    }
    for (int idx = tid; idx < KIN * CPC; idx += THREADS) {
        int k4 = idx >> 8, c = (idx >> 2) & 63, e = idx & 3;
        int k  = k4 * 4 + e;
        int gc = (c >> 4) * H_ + hg0 + (c & 15);
        sW2[idx] = (k < H_) ? Wx_in[k * G4H + gc] : Wh_in[(k - H_) * G4H + gc];
    }
    if (tid < CPC) {
        int gc = (tid >> 4) * H_ + hg0 + (tid & 15);
        sB1[tid] = b_out[gc];
        sB2[tid] = b_in[gc];
    }
    if (tid < BPG * HPG) {
        sC[tid] = 0.0f; sCN[tid] = 0.0f;
        int b = tid >> 4, h = tid & 15;
        __stcg(&g_h[(bg0 + b) * H_ + hg0 + h], 0.0f);
    }
    __syncthreads();
    cluster_sync();   // transpose slices + g_h zeros visible cluster-wide

    // ================= phase 2: recurrence =================
    const int c = tid & 63;          // gate column (local)
    const int q = tid >> 6;          // k-eighth 0..7
    const float* xTbg = g_xT + (size_t)bi * S_ * (BPG * I_);

    for (int t = 0; t < S_; t++) {
        // ---- stage 1: sX1[k][b] = [x_t | h] ----
        {
            const float* xrow = xTbg + (size_t)t * (BPG * I_);
            { // x part: 512 floats, coalesced read
                float v = xrow[tid];
                int b = tid >> 6, k = tid & 63;
                sX1[k * 12 + b] = v;
            }
#pragma unroll
            for (int rep = 0; rep < 2; rep++) { // h part: 1024 floats
                int idx = tid + rep * THREADS;
                int b = idx >> 7, h = idx & 127;
                sX1[(I_ + h) * 12 + b] = __ldcg(&g_h[(bg0 + b) * H_ + h]);
            }
        }
        __syncthreads();

        // ---- matvec 1: partials over k-eighth (24 k = 6 float4 chunks) ----
        {
            float acc[BPG];
#pragma unroll
            for (int b = 0; b < BPG; b++) acc[b] = 0.0f;
            const float4* w4 = (const float4*)sW1 + (q * 6) * 64 + c;
            const float*  xq = sX1 + (q * 24) * 12;
#pragma unroll
            for (int j = 0; j < 6; j++) {
                float4 w = w4[j * 64];
#pragma unroll
                for (int kk = 0; kk < 4; kk++) {
                    float wv = (kk == 0) ? w.x : (kk == 1) ? w.y : (kk == 2) ? w.z : w.w;
                    const float* xr = xq + (j * 4 + kk) * 12;
                    float4 xa = *(const float4*)(xr);
                    float4 xb = *(const float4*)(xr + 4);
                    acc[0] = fmaf(wv, xa.x, acc[0]); acc[1] = fmaf(wv, xa.y, acc[1]);
                    acc[2] = fmaf(wv, xa.z, acc[2]); acc[3] = fmaf(wv, xa.w, acc[3]);
                    acc[4] = fmaf(wv, xb.x, acc[4]); acc[5] = fmaf(wv, xb.y, acc[5]);
                    acc[6] = fmaf(wv, xb.z, acc[6]); acc[7] = fmaf(wv, xb.w, acc[7]);
                }
            }
#pragma unroll
            for (int b = 0; b < BPG; b++) sP[q * 640 + b * 80 + c] = acc[b];
        }
        __syncthreads();

        // ---- act 1 (combine partials + gates) ----
        if (tid < BPG * HPG) {
            int b = tid >> 4, h = tid & 15;
            float gs[4];
#pragma unroll
            for (int g = 0; g < 4; g++) {
                int cc = g * 16 + h;
                float s = sB1[cc];
#pragma unroll
                for (int qq = 0; qq < 8; qq++) s += sP[qq * 640 + b * 80 + cc];
                gs[g] = s;
            }
            float iv = sigf(gs[0]), fv = sigf(gs[1]), ov = sigf(gs[2]), gv = tanh_(gs[3]);
            float xin = iv * gv;
            float hin = fv * sC[tid];
            sO[tid] = ov;
            int gidx = (bg0 + b) * H_ + hg0 + h;
            __stcg(&g_xin[gidx], xin);
            __stcg(&g_hin[gidx], hin);
        }
        __syncthreads();
        cluster_sync();   // publish x_in / h_in (release) + CTA barrier

        // ---- stage 2: sX2[k][b] = [x_in | h_in] ----
#pragma unroll
        for (int rep = 0; rep < 4; rep++) {
            int idx = tid + rep * THREADS;   // 2048 floats
            int b = idx >> 8, k = idx & 255;
            float v = (k < H_) ? __ldcg(&g_xin[(bg0 + b) * H_ + k])
                               : __ldcg(&g_hin[(bg0 + b) * H_ + (k - H_)]);
            sX2[k * 12 + b] = v;
        }
        __syncthreads();

        // ---- matvec 2: 32 k per thread = 8 chunks ----
        {
            float acc[BPG];
#pragma unroll
            for (int b = 0; b < BPG; b++) acc[b] = 0.0f;
            const float4* w4 = (const float4*)sW2 + (q * 8) * 64 + c;
            const float*  xq = sX2 + (q * 32) * 12;
#pragma unroll
            for (int j = 0; j < 8; j++) {
                float4 w = w4[j * 64];
#pragma unroll
                for (int kk = 0; kk < 4; kk++) {
                    float wv = (kk == 0) ? w.x : (kk == 1) ? w.y : (kk == 2) ? w.z : w.w;
                    const float* xr = xq + (j * 4 + kk) * 12;
                    float4 xa = *(const float4*)(xr);
                    float4 xb = *(const float4*)(xr + 4);
                    acc[0] = fmaf(wv, xa.x, acc[0]); acc[1] = fmaf(wv, xa.y, acc[1]);
                    acc[2] = fmaf(wv, xa.z, acc[2]); acc[3] = fmaf(wv, xa.w, acc[3]);
                    acc[4] = fmaf(wv, xb.x, acc[4]); acc[5] = fmaf(wv, xb.y, acc[5]);
                    acc[6] = fmaf(wv, xb.z, acc[6]); acc[7] = fmaf(wv, xb.w, acc[7]);
                }
            }
#pragma unroll
            for (int b = 0; b < BPG; b++) sP[q * 640 + b * 80 + c] = acc[b];
        }
        __syncthreads();

        // ---- act 2 ----
        if (tid < BPG * HPG) {
            int b = tid >> 4, h = tid & 15;
            float gs[4];
#pragma unroll
            for (int g = 0; g < 4; g++) {
                int cc = g * 16 + h;
                float s = sB2[cc];
#pragma unroll
                for (int qq = 0; qq < 8; qq++) s += sP[qq * 640 + b * 80 + cc];
                gs[g] = s;
            }
            float cn = sigf(gs[1]) * sCN[tid] + sigf(gs[0]) * tanh_(gs[3]);
            float cv = sigf(gs[2]) * tanh_(cn);
            float hv = sO[tid] * tanh_(cv);
            sCN[tid] = cn;
            sC[tid]  = cv;
            int bg = bg0 + b, hg = hg0 + h;
            __stcg(&g_h[bg * H_ + hg], hv);
            g_hs[((size_t)bg * S_ + t) * H_ + hg] = hv;
        }
        __syncthreads();
        cluster_sync();   // publish h for next step + CTA barrier
    }

    // ================= phase 3: cluster-local projection =================
    // This CTA: batches bg0..bg0+7, t in [hj*256, hj*256+256). 2048 rows.
    {
        float* sWt = smem + OFF_W1;      // W_lin^T: [k 128][o 64] = 8192 f
        float* sTile = smem + OFF_W2;    // h tile: [64][132] = 8448 f
        float* sBL = smem + OFF_B1;      // 64 f
        for (int idx = tid; idx < H_ * O_; idx += THREADS) {
            int o = idx & 63, k = idx >> 6;
            sWt[k * 64 + o] = W_lin[o * H_ + k];
        }
        if (tid < O_) sBL[tid] = b_lin[tid];
        __syncthreads();

        const int t0 = hj * 256;
        const int row = tid >> 3;        // 0..63
        const int cg  = tid & 7;         // 8 cols each
        for (int it = 0; it < 32; it++) {
            int b   = it >> 2;
            int tr0 = t0 + (it & 3) * 64;
            const float* src = g_hs + ((size_t)(bg0 + b) * S_ + tr0) * H_;
            for (int idx = tid; idx < 64 * H_; idx += THREADS) {
                int r = idx >> 7, k = idx & 127;
                sTile[r * 132 + k] = src[idx];
            }
            __syncthreads();

            float accp[8];
#pragma unroll
            for (int j = 0; j < 8; j++) accp[j] = sBL[cg * 8 + j];
            const float* hrow = sTile + row * 132;
#pragma unroll 8
            for (int k4 = 0; k4 < 32; k4++) {
                float4 hx = *(const float4*)(hrow + k4 * 4);
#pragma unroll
                for (int kk = 0; kk < 4; kk++) {
                    float hv = (kk == 0) ? hx.x : (kk == 1) ? hx.y : (kk == 2) ? hx.z : hx.w;
                    const float* wr = sWt + (k4 * 4 + kk) * 64 + cg * 8;
                    float4 w0 = *(const float4*)(wr);
                    float4 w1 = *(const float4*)(wr + 4);
                    accp[0] = fmaf(hv, w0.x, accp[0]); accp[1] = fmaf(hv, w0.y, accp[1]);
                    accp[2] = fmaf(hv, w0.z, accp[2]); accp[3] = fmaf(hv, w0.w, accp[3]);
                    accp[4] = fmaf(hv, w1.x, accp[4]); accp[5] = fmaf(hv, w1.y, accp[5]);
                    accp[6] = fmaf(hv, w1.z, accp[6]); accp[7] = fmaf(hv, w1.w, accp[7]);
                }
            }
            float* orow = out + ((size_t)(bg0 + b) * S_ + tr0 + row) * O_ + cg * 8;
            *(float4*)(orow)     = make_float4(accp[0], accp[1], accp[2], accp[3]);
            *(float4*)(orow + 4) = make_float4(accp[4], accp[5], accp[6], accp[7]);
            __syncthreads();
        }
    }
}

// ---------------- launch ----------------
extern "C" void kernel_launch(void* const* d_in, const int* in_sizes, int n_in,
                              void* d_out, int out_size)
{
    const float* x      = (const float*)d_in[0];
    const float* Wx_out = (const float*)d_in[1];
    const float* Wh_out = (const float*)d_in[2];
    const float* b_out  = (const float*)d_in[3];
    const float* Wx_in  = (const float*)d_in[4];
    const float* Wh_in  = (const float*)d_in[5];
    const float* b_in   = (const float*)d_in[6];
    const float* W_lin  = (const float*)d_in[7];
    const float* b_lin  = (const float*)d_in[8];
    float* out = (float*)d_out;

    (void)cudaFuncSetAttribute(nlstm_fused,
                               cudaFuncAttributeMaxDynamicSharedMemorySize, SMEM_BYTES);
    nlstm_fused<<<dim3(GH, GB), THREADS, SMEM_BYTES>>>(
        x, Wx_out, Wh_out, b_out, Wx_in, Wh_in, b_in, W_lin, b_lin, out);
}